// round 15
// baseline (speedup 1.0000x reference)
#include <cuda_runtime.h>

// Problem constants (fixed by reference)
#define BATCH   1000
#define NUE_    4
#define K_      500
#define M_      500
#define N_      1000
#define NSYM_   250
#define NEDGE_  2000
#define NINFOE_ 1500
#define NITER_  5

// Static scratch
__device__ float         g_llr[BATCH * NUE_ * N_];   // channel LLRs
__device__ unsigned char g_par[BATCH * NUE_ * M_];   // parity bits (2MB)
__device__ short g_eoff[M_ + 1];
__device__ short g_elist[NINFOE_];

// ---------------------------------------------------------------------------
// Hybrid tanh (validated R3-R14) — init only.
// ---------------------------------------------------------------------------
__device__ __forceinline__ float tanh_clip_half(float x) {
    x = fminf(fmaxf(x, -9.9f), 9.9f);
    float ax = fabsf(x);
    float x2 = x * x;
    float num = x * fmaf(x2, fmaf(x2, 1.0f, 105.0f), 945.0f);
    float den = fmaf(x2, fmaf(x2, 15.0f, 420.0f), 945.0f);
    float tp  = __fdividef(num, den);
    float e   = __expf(2.0f * ax);
    float te  = copysignf(1.0f - __fdividef(2.0f, e + 1.0f), x);
    float t   = (ax < 1.0f) ? tp : te;
    return (t >= 0.f) ? fmaxf(t, 1e-7f) : fminf(t, -1e-7f);
}

__device__ __forceinline__ float clip999(float x) {
    return fminf(fmaxf(x, -0.999999f), 0.999999f);
}

__device__ __forceinline__ float msg_floor(float t) {
    return (t >= 0.f) ? fmaxf(t, 1e-7f) : fminf(t, -1e-7f);
}

// Variable update, one lane (validated R11-R14: rel_err 0.0).
__device__ __forceinline__ void var_update(float m0, float m1, float m2,
                                           float p0, float p1, float p2,
                                           float el,
                                           float& o0, float& o1, float& o2) {
    float inv = __fdividef(1.0f, m0 * m1 * m2);
    float r0 = clip999(p0 * (m1 * m2) * inv);
    float r1 = clip999(p1 * (m0 * m2) * inv);
    float r2 = clip999(p2 * (m0 * m1) * inv);
    float np0 = 1.0f + r0, nm0 = 1.0f - r0;
    float np1 = 1.0f + r1, nm1 = 1.0f - r1;
    float np2 = 1.0f + r2, nm2 = 1.0f - r2;
    float e0 = el * np0;
    float A0 = el * (np1 * np2), A1 = e0 * np2, A2 = e0 * np1;
    float B0 = nm1 * nm2,        B1 = nm0 * nm2, B2 = nm0 * nm1;
    o0 = msg_floor(__fdividef(A0 - B0, A0 + B0));
    o1 = msg_floor(__fdividef(A1 - B1, A1 + B1));
    o2 = msg_floor(__fdividef(A2 - B2, A2 + B2));
}

// Final decision, one lane: bit = (e^{vtot} < 1) <=> el*Prod(np) < Prod(nm)
__device__ __forceinline__ float var_decide(float m0, float m1, float m2,
                                            float p0, float p1, float p2,
                                            float el) {
    float inv = __fdividef(1.0f, m0 * m1 * m2);
    float r0 = clip999(p0 * (m1 * m2) * inv);
    float r1 = clip999(p1 * (m0 * m2) * inv);
    float r2 = clip999(p2 * (m0 * m1) * inv);
    float U = el * ((1.0f + r0) * (1.0f + r1)) * (1.0f + r2);
    float D = ((1.0f - r0) * (1.0f - r1)) * (1.0f - r2);
    return (U < D) ? 1.0f : 0.0f;
}

// One check's product step
__device__ __forceinline__ void check_step(int m, int o0, int o1,
                                           const float4* __restrict__ sT,
                                           const float4* __restrict__ sTp,
                                           float4* __restrict__ sP,
                                           const short* __restrict__ selist) {
    float4 p = sTp[m];
    for (int q = o0; q < o1; q++) {
        float4 tt = sT[selist[q]];
        p.x *= tt.x; p.y *= tt.y; p.z *= tt.z; p.w *= tt.w;
    }
    sP[m] = p;
}

// One variable's full step (update or final decision)
__device__ __forceinline__ void var_step(int v, int c0, int c1, int c2,
                                         float4* __restrict__ sT,
                                         const float4* __restrict__ sP,
                                         const float4* __restrict__ sEL,
                                         bool last, float* __restrict__ oh) {
    float4 m0 = sT[3 * v], m1 = sT[3 * v + 1], m2 = sT[3 * v + 2];
    float4 p0 = sP[c0], p1 = sP[c1], p2 = sP[c2];
    float4 el = sEL[v];
    if (!last) {
        float4 o0, o1, o2;
        var_update(m0.x, m1.x, m2.x, p0.x, p1.x, p2.x, el.x, o0.x, o1.x, o2.x);
        var_update(m0.y, m1.y, m2.y, p0.y, p1.y, p2.y, el.y, o0.y, o1.y, o2.y);
        var_update(m0.z, m1.z, m2.z, p0.z, p1.z, p2.z, el.z, o0.z, o1.z, o2.z);
        var_update(m0.w, m1.w, m2.w, p0.w, p1.w, p2.w, el.w, o0.w, o1.w, o2.w);
        sT[3 * v] = o0; sT[3 * v + 1] = o1; sT[3 * v + 2] = o2;
    } else {
        oh[0 * K_ + v] = var_decide(m0.x, m1.x, m2.x, p0.x, p1.x, p2.x, el.x);
        oh[1 * K_ + v] = var_decide(m0.y, m1.y, m2.y, p0.y, p1.y, p2.y, el.y);
        oh[2 * K_ + v] = var_decide(m0.z, m1.z, m2.z, p0.z, p1.z, p2.z, el.z);
        oh[3 * K_ + v] = var_decide(m0.w, m1.w, m2.w, p0.w, p1.w, p2.w, el.w);
    }
}

// ---------------------------------------------------------------------------
// Encode kernel: block 0 builds the CSR; every block stages info bits,
// emits the bf output, computes parity via shared atomicXor, writes g_par.
// Pure memory + XOR — no LMMSE here.
// ---------------------------------------------------------------------------
__global__ __launch_bounds__(256)
void encode_kernel(const int* __restrict__ bin,
                   const int* __restrict__ cn,
                   float* __restrict__ out_bf)
{
    __shared__ char scratch[12032];

    const int b = blockIdx.x;
    const int t = threadIdx.x;
    const int lane = t & 31, wid = t >> 5;

    // ---- block 0 only: build global CSR (aliases scratch; before bits) ----
    if (b == 0) {
        int*   cnt  = (int*)scratch;            // [M_]   2000
        int*   base = (int*)(scratch + 2000);   // [M_]   2000
        int*   wsum = (int*)(scratch + 4000);   // [8]      32
        short* sel  = (short*)(scratch + 4032); // [NINFOE_] 3000

        for (int m = t; m < M_; m += 256) cnt[m] = 0;
        __syncthreads();
        for (int e = t; e < NINFOE_; e += 256) atomicAdd(&cnt[cn[e]], 1);
        __syncthreads();
        int v0 = (2 * t     < M_) ? cnt[2 * t]     : 0;
        int v1 = (2 * t + 1 < M_) ? cnt[2 * t + 1] : 0;
        int s = v0 + v1, x = s;
#pragma unroll
        for (int d = 1; d < 32; d <<= 1) {
            int nn = __shfl_up_sync(0xffffffffu, x, d);
            if (lane >= d) x += nn;
        }
        if (lane == 31) wsum[wid] = x;
        __syncthreads();
        if (wid == 0) {
            int s2 = (lane < 8) ? wsum[lane] : 0;
#pragma unroll
            for (int d = 1; d < 8; d <<= 1) {
                int nn = __shfl_up_sync(0xffffffffu, s2, d);
                if (lane >= d) s2 += nn;
            }
            if (lane < 8) wsum[lane] = s2;
        }
        __syncthreads();
        int ex = x + ((wid > 0) ? wsum[wid - 1] : 0) - s;
        if (2 * t     < M_) { base[2 * t]     = ex;      g_eoff[2 * t]     = (short)ex; }
        if (2 * t + 1 < M_) { base[2 * t + 1] = ex + v0; g_eoff[2 * t + 1] = (short)(ex + v0); }
        if (t == 0) g_eoff[M_] = (short)NINFOE_;
        __syncthreads();
        for (int m = t; m < M_; m += 256) cnt[m] = 0;
        __syncthreads();
        for (int e = t; e < NINFOE_; e += 256) {
            int c = cn[e];
            int sl = atomicAdd(&cnt[c], 1);
            sel[base[c] + sl] = (short)e;
        }
        __syncthreads();
        for (int m = t; m < M_; m += 256) {
            int o0 = base[m], o1 = o0 + cnt[m];
            for (int i = o0 + 1; i < o1; i++) {
                short vv = sel[i];
                int j = i - 1;
                while (j >= o0 && sel[j] > vv) { sel[j + 1] = sel[j]; j--; }
                sel[j + 1] = vv;
            }
        }
        __syncthreads();
        for (int e = t; e < NINFOE_; e += 256) g_elist[e] = sel[e];
        __syncthreads();
    }

    unsigned char* bits = (unsigned char*)scratch;   // [NUE_*K_] = 2000
    int* sp = (int*)(scratch + 2000);                // [NUE_*M_] = 8000

    const int* bb = bin + (size_t)b * NUE_ * K_;
    float* of = out_bf + (size_t)b * NUE_ * K_;
    for (int i = t; i < NUE_ * K_; i += 256) {
        int bit = bb[i];
        bits[i] = (unsigned char)bit;
        of[i] = (float)bit;
    }
    for (int i = t; i < NUE_ * M_; i += 256) sp[i] = 0;
    __syncthreads();

    // parity via atomicXor over info edges (vn[e] = e/3 analytically)
    for (int e = t; e < NINFOE_; e += 256) {
        int c = cn[e], v = e / 3;
#pragma unroll
        for (int ue = 0; ue < 4; ue++)
            if (bits[ue * K_ + v]) atomicXor(&sp[ue * M_ + c], 1);
    }
    __syncthreads();
    unsigned char* gp = g_par + (size_t)b * NUE_ * M_;
    for (int i = t; i < NUE_ * M_; i += 256)
        gp[i] = (unsigned char)sp[i];
}

// ---------------------------------------------------------------------------
// Flat LMMSE: one thread per resource element, no smem, no barriers.
// Bits come straight from bin (s<125: all-info positions) or g_par.
// ---------------------------------------------------------------------------
__global__ __launch_bounds__(256, 4)
void lmmse_flat_kernel(const int* __restrict__ bin,
                       const float4* __restrict__ hre4, const float4* __restrict__ him4,
                       const float4* __restrict__ nre4, const float4* __restrict__ nim4,
                       const float* __restrict__ ebno)
{
    const int r = blockIdx.x * 256 + threadIdx.x;
    if (r >= BATCH * NSYM_) return;
    const int b = r / NSYM_;
    const int s = r - b * NSYM_;

    const float no  = 1.0f / (exp10f(ebno[0] * 0.1f) * 2.0f);
    const float is2 = 0.70710678118654752440f;
    const float s10 = 0.31622776601683794f;

    float hr[4][4], hi[4][4];
#pragma unroll
    for (int i = 0; i < 4; i++) {
        float4 vr = hre4[r * 4 + i];
        float4 vi = him4[r * 4 + i];
        hr[i][0] = vr.x * is2; hr[i][1] = vr.y * is2; hr[i][2] = vr.z * is2; hr[i][3] = vr.w * is2;
        hi[i][0] = vi.x * is2; hi[i][1] = vi.y * is2; hi[i][2] = vi.z * is2; hi[i][3] = vi.w * is2;
    }

    // modulate: positions 4s..4s+3 are all-info (s<125) or all-parity
    float xr[4], xi[4];
    if (s < 125) {
#pragma unroll
        for (int j = 0; j < 4; j++) {
            int4 cb = *(const int4*)&bin[((size_t)b * NUE_ + j) * K_ + 4 * s];
            xr[j] = (float)((1 - 2 * cb.x) * (1 + 2 * cb.z)) * s10;
            xi[j] = (float)((1 - 2 * cb.y) * (1 + 2 * cb.w)) * s10;
        }
    } else {
#pragma unroll
        for (int j = 0; j < 4; j++) {
            uchar4 cb = *(const uchar4*)&g_par[((size_t)b * NUE_ + j) * M_ + 4 * s - K_];
            xr[j] = (float)((1 - 2 * (int)cb.x) * (1 + 2 * (int)cb.z)) * s10;
            xi[j] = (float)((1 - 2 * (int)cb.y) * (1 + 2 * (int)cb.w)) * s10;
        }
    }

    const float ns = sqrtf(no * 0.5f);
    float4 wr4 = nre4[r], wi4 = nim4[r];
    float yr[4] = {wr4.x * ns, wr4.y * ns, wr4.z * ns, wr4.w * ns};
    float yi[4] = {wi4.x * ns, wi4.y * ns, wi4.z * ns, wi4.w * ns};
#pragma unroll
    for (int i = 0; i < 4; i++)
#pragma unroll
        for (int j = 0; j < 4; j++) {
            yr[i] += hr[i][j] * xr[j] - hi[i][j] * xi[j];
            yi[i] += hr[i][j] * xi[j] + hi[i][j] * xr[j];
        }

    float rr[4], ri[4];
#pragma unroll
    for (int j = 0; j < 4; j++) {
        float ar = 0.f, ai = 0.f;
#pragma unroll
        for (int i = 0; i < 4; i++) {
            ar += hr[i][j] * yr[i] + hi[i][j] * yi[i];
            ai += hr[i][j] * yi[i] - hi[i][j] * yr[i];
        }
        rr[j] = ar; ri[j] = ai;
    }

    float Br[4][4], Bi[4][4];
#pragma unroll
    for (int j = 0; j < 4; j++)
#pragma unroll
        for (int k = 0; k < 4; k++) {
            if (k > j) continue;
            float ar = (j == k) ? no : 0.f;
            float ai = 0.f;
#pragma unroll
            for (int i = 0; i < 4; i++) {
                ar += hr[i][j] * hr[i][k] + hi[i][j] * hi[i][k];
                ai += hr[i][j] * hi[i][k] - hi[i][j] * hr[i][k];
            }
            Br[j][k] = ar; Bi[j][k] = ai;
        }

    float rk[4];
#pragma unroll
    for (int k = 0; k < 4; k++) {
        float v = Br[k][k];
#pragma unroll
        for (int j = 0; j < 4; j++)
            if (j < k) v -= Br[k][j] * Br[k][j] + Bi[k][j] * Bi[k][j];
        float inv = rsqrtf(v);
        rk[k] = inv;
#pragma unroll
        for (int i = 0; i < 4; i++) {
            if (i <= k) continue;
            float cr = Br[i][k], ci = Bi[i][k];
#pragma unroll
            for (int j = 0; j < 4; j++)
                if (j < k) {
                    cr -= Br[i][j] * Br[k][j] + Bi[i][j] * Bi[k][j];
                    ci -= Bi[i][j] * Br[k][j] - Br[i][j] * Bi[k][j];
                }
            Br[i][k] = cr * inv; Bi[i][k] = ci * inv;
        }
    }

    float vr_[4], vi_[4];
#pragma unroll
    for (int i = 0; i < 4; i++) {
        float ar = rr[i], ai = ri[i];
#pragma unroll
        for (int j = 0; j < 4; j++)
            if (j < i) {
                ar -= Br[i][j] * vr_[j] - Bi[i][j] * vi_[j];
                ai -= Br[i][j] * vi_[j] + Bi[i][j] * vr_[j];
            }
        vr_[i] = ar * rk[i]; vi_[i] = ai * rk[i];
    }
    float xrw[4], xiw[4];
#pragma unroll
    for (int ii = 0; ii < 4; ii++) {
        int i = 3 - ii;
        float ar = vr_[i], ai = vi_[i];
#pragma unroll
        for (int j = 0; j < 4; j++)
            if (j > i) {
                ar -= Br[j][i] * xrw[j] + Bi[j][i] * xiw[j];
                ai -= Br[j][i] * xiw[j] - Bi[j][i] * xrw[j];
            }
        xrw[i] = ar * rk[i]; xiw[i] = ai * rk[i];
    }

    float dj[4];
#pragma unroll
    for (int j = 0; j < 4; j++) {
        float wr[4], wi[4];
#pragma unroll
        for (int i = 0; i < 4; i++) { wr[i] = 0.f; wi[i] = 0.f; }
        wr[j] = rk[j];
        float acc = rk[j] * rk[j];
#pragma unroll
        for (int i = 0; i < 4; i++) {
            if (i <= j) continue;
            float sr = 0.f, si = 0.f;
#pragma unroll
            for (int q = 0; q < 4; q++)
                if (q >= j && q < i) {
                    sr += Br[i][q] * wr[q] - Bi[i][q] * wi[q];
                    si += Br[i][q] * wi[q] + Bi[i][q] * wr[q];
                }
            wr[i] = -sr * rk[i]; wi[i] = -si * rk[i];
            acc += wr[i] * wr[i] + wi[i] * wi[i];
        }
        dj[j] = acc;
    }

#pragma unroll
    for (int c = 0; c < 4; c++) {
        float d = 1.0f - no * dj[c];
        float invd = 1.0f / d;
        float xhr = xrw[c] * invd, xhi = xiw[c] * invd;
        float noeff = fmaxf(invd - 1.0f, 1e-12f);
        float inoe = 1.0f / noeff;

        float a1  = xhr - s10,  a3  = xhr - 3.f * s10;
        float am1 = xhr + s10,  am3 = xhr + 3.f * s10;
        float f1 = -(a1 * a1), f3 = -(a3 * a3), fm1 = -(am1 * am1), fm3 = -(am3 * am3);
        float g1_ = xhi - s10,  g3_ = xhi - 3.f * s10;
        float gm1_ = xhi + s10, gm3_ = xhi + 3.f * s10;
        float g1 = -(g1_ * g1_), g3 = -(g3_ * g3_), gm1 = -(gm1_ * gm1_), gm3 = -(gm3_ * gm3_);

        float4 out = make_float4((fmaxf(f1, f3)  - fmaxf(fm1, fm3)) * inoe,
                                 (fmaxf(g1, g3)  - fmaxf(gm1, gm3)) * inoe,
                                 (fmaxf(f1, fm1) - fmaxf(f3, fm3))  * inoe,
                                 (fmaxf(g1, gm1) - fmaxf(g3, gm3))  * inoe);
        *(float4*)&g_llr[(size_t)(b * NUE_ + c) * N_ + 4 * s] = out;
    }
}

// ---------------------------------------------------------------------------
// Decoder (unchanged from R14): one block per batch element, 256 threads,
// each owning TWO variables and TWO checks. (256,4): 64-reg budget,
// spill-free, 2 independent chains per thread.
// ---------------------------------------------------------------------------
extern __shared__ unsigned char dynsmem[];
#define DEC_SMEM (24000 + 8000 + 8000 + 8000 + 3000)

__global__ __launch_bounds__(256, 4)
void decode_kernel(const int* __restrict__ cn, float* __restrict__ out_bhat) {
    float4* sT  = (float4*)dynsmem;          // [NINFOE_] v->c message tanh
    float4* sP  = sT + NINFOE_;              // [M_]  check products
    float4* sTp = sP + M_;                   // [M_]  parity-edge tanh (invariant)
    float4* sEL = sTp + M_;                  // [K_]  clamped exp(Lch)
    short* selist = (short*)(sEL + K_);      // [NINFOE_]

    const int b = blockIdx.x;
    const int t = threadIdx.x;
    const float* Lb = g_llr + (size_t)b * NUE_ * N_;

    for (int e = t; e < NINFOE_; e += 256) selist[e] = g_elist[e];

    for (int v = t; v < K_; v += 256) {
        float4 l;
        l.x = Lb[0 * N_ + v]; l.y = Lb[1 * N_ + v];
        l.z = Lb[2 * N_ + v]; l.w = Lb[3 * N_ + v];
        float4 el;
        el.x = fminf(__expf(l.x), 1e30f); el.y = fminf(__expf(l.y), 1e30f);
        el.z = fminf(__expf(l.z), 1e30f); el.w = fminf(__expf(l.w), 1e30f);
        sEL[v] = el;
        float4 m;
        m.x = tanh_clip_half(l.x * 0.5f);
        m.y = tanh_clip_half(l.y * 0.5f);
        m.z = tanh_clip_half(l.z * 0.5f);
        m.w = tanh_clip_half(l.w * 0.5f);
        sT[3 * v] = m; sT[3 * v + 1] = m; sT[3 * v + 2] = m;
    }
    for (int m = t; m < M_; m += 256) {
        float4 lp;
        lp.x = Lb[0 * N_ + K_ + m]; lp.y = Lb[1 * N_ + K_ + m];
        lp.z = Lb[2 * N_ + K_ + m]; lp.w = Lb[3 * N_ + K_ + m];
        float4 tp;
        tp.x = tanh_clip_half(lp.x * 0.5f);
        tp.y = tanh_clip_half(lp.y * 0.5f);
        tp.z = tanh_clip_half(lp.z * 0.5f);
        tp.w = tanh_clip_half(lp.w * 0.5f);
        sTp[m] = tp;
    }

    const bool hasB = (t + 256 < K_);   // K_ == M_ == 500
    const int vA = t, vB = t + 256;
    int c0a = cn[3 * vA], c1a = cn[3 * vA + 1], c2a = cn[3 * vA + 2];
    int c0b = 0, c1b = 0, c2b = 0;
    if (hasB) { c0b = cn[3 * vB]; c1b = cn[3 * vB + 1]; c2b = cn[3 * vB + 2]; }
    int coa0 = g_eoff[vA], coa1 = g_eoff[vA + 1];
    int cob0 = 0, cob1 = 0;
    if (hasB) { cob0 = g_eoff[vB]; cob1 = g_eoff[vB + 1]; }
    __syncthreads();

    float* oh = out_bhat + (size_t)b * NUE_ * K_;

    for (int it = 0; it < NITER_; it++) {
        check_step(vA, coa0, coa1, sT, sTp, sP, selist);
        if (hasB) check_step(vB, cob0, cob1, sT, sTp, sP, selist);
        __syncthreads();
        bool last = (it == NITER_ - 1);
        var_step(vA, c0a, c1a, c2a, sT, sP, sEL, last, oh);
        if (hasB) var_step(vB, c0b, c1b, c2b, sT, sP, sEL, last, oh);
        if (!last) __syncthreads();
    }
}

// ---------------------------------------------------------------------------
extern "C" void kernel_launch(void* const* d_in, const int* in_sizes, int n_in,
                              void* d_out, int out_size) {
    int shift = 10 - n_in;
    const float* ebno = (const float*)d_in[1 - shift];
    const int*   b    = (const int*)  d_in[2 - shift];
    const int*   cn   = (const int*)  d_in[4 - shift];
    const float* h_re = (const float*)d_in[6 - shift];
    const float* h_im = (const float*)d_in[7 - shift];
    const float* n_re = (const float*)d_in[8 - shift];
    const float* n_im = (const float*)d_in[9 - shift];

    float* out_bf = (float*)d_out;                       // (batch, NUE, K)
    float* out_bh = (float*)d_out + BATCH * NUE_ * K_;   // (batch, NUE, K)

    cudaFuncSetAttribute(decode_kernel, cudaFuncAttributeMaxDynamicSharedMemorySize, DEC_SMEM);

    encode_kernel<<<BATCH, 256>>>(b, cn, out_bf);

    const int nr = BATCH * NSYM_;
    lmmse_flat_kernel<<<(nr + 255) / 256, 256>>>(b,
                                                 (const float4*)h_re, (const float4*)h_im,
                                                 (const float4*)n_re, (const float4*)n_im,
                                                 ebno);

    decode_kernel<<<BATCH, 256, DEC_SMEM>>>(cn, out_bh);
}

// round 16
// speedup vs baseline: 1.0529x; 1.0529x over previous
#include <cuda_runtime.h>

// Problem constants (fixed by reference)
#define BATCH   1000
#define NUE_    4
#define K_      500
#define M_      500
#define N_      1000
#define NSYM_   250
#define NEDGE_  2000
#define NINFOE_ 1500
#define NITER_  5

typedef unsigned long long u64;
#define ONE2 0x3F8000003F800000ULL   // pack(1.0f, 1.0f)
#define NEG2 0xBF800000BF800000ULL   // pack(-1.0f, -1.0f)

// Static scratch
__device__ float g_llr[BATCH * NUE_ * N_];   // channel LLRs
__device__ short g_eoff[M_ + 1];
__device__ short g_elist[NINFOE_];

// ---------------------------------------------------------------------------
// Packed f32x2 helpers (Blackwell packed fp32 pipe; bit-identical per lane)
// ---------------------------------------------------------------------------
__device__ __forceinline__ u64 f2pack(float lo, float hi) {
    u64 r; asm("mov.b64 %0, {%1, %2};" : "=l"(r) : "f"(lo), "f"(hi)); return r;
}
__device__ __forceinline__ void f2unpack(u64 v, float& lo, float& hi) {
    asm("mov.b64 {%0, %1}, %2;" : "=f"(lo), "=f"(hi) : "l"(v));
}
__device__ __forceinline__ u64 f2mul(u64 a, u64 b) {
    u64 r; asm("mul.rn.f32x2 %0, %1, %2;" : "=l"(r) : "l"(a), "l"(b)); return r;
}
__device__ __forceinline__ u64 f2add(u64 a, u64 b) {
    u64 r; asm("add.rn.f32x2 %0, %1, %2;" : "=l"(r) : "l"(a), "l"(b)); return r;
}
__device__ __forceinline__ u64 f2fma(u64 a, u64 b, u64 c) {
    u64 r; asm("fma.rn.f32x2 %0, %1, %2, %3;" : "=l"(r) : "l"(a), "l"(b), "l"(c)); return r;
}

// ---------------------------------------------------------------------------
// Hybrid tanh (validated R3-R15) — init only.
// ---------------------------------------------------------------------------
__device__ __forceinline__ float tanh_clip_half(float x) {
    x = fminf(fmaxf(x, -9.9f), 9.9f);
    float ax = fabsf(x);
    float x2 = x * x;
    float num = x * fmaf(x2, fmaf(x2, 1.0f, 105.0f), 945.0f);
    float den = fmaf(x2, fmaf(x2, 15.0f, 420.0f), 945.0f);
    float tp  = __fdividef(num, den);
    float e   = __expf(2.0f * ax);
    float te  = copysignf(1.0f - __fdividef(2.0f, e + 1.0f), x);
    float t   = (ax < 1.0f) ? tp : te;
    return (t >= 0.f) ? fmaxf(t, 1e-7f) : fminf(t, -1e-7f);
}

__device__ __forceinline__ float clip999(float x) {
    return fminf(fmaxf(x, -0.999999f), 0.999999f);
}
__device__ __forceinline__ float msg_floor(float t) {
    return (t >= 0.f) ? fmaxf(t, 1e-7f) : fminf(t, -1e-7f);
}
__device__ __forceinline__ u64 f2clip(u64 v) {
    float lo, hi; f2unpack(v, lo, hi);
    return f2pack(clip999(lo), clip999(hi));
}
// msg = floor((A-B)/(A+B)); A-B via fma(B,-1,A) (single rounding == FADD)
__device__ __forceinline__ u64 f2msg(u64 A, u64 B) {
    u64 num = f2fma(B, NEG2, A);
    u64 den = f2add(A, B);
    float nlo, nhi, dlo, dhi;
    f2unpack(num, nlo, nhi); f2unpack(den, dlo, dhi);
    return f2pack(msg_floor(__fdividef(nlo, dlo)), msg_floor(__fdividef(nhi, dhi)));
}

// Variable update for a LANE PAIR (2 codewords packed). Same math/rounding as
// the R11-R15 scalar var_update (validated rel_err 0.0).
__device__ __forceinline__ void var_update_pair(u64 m0, u64 m1, u64 m2,
                                                u64 p0, u64 p1, u64 p2, u64 el,
                                                u64& o0, u64& o1, u64& o2) {
    u64 t12 = f2mul(m1, m2);
    u64 t02 = f2mul(m0, m2);
    u64 t01 = f2mul(m0, m1);
    u64 pr  = f2mul(t01, m2);            // (m0*m1)*m2, as scalar version
    float plo, phi; f2unpack(pr, plo, phi);
    u64 inv = f2pack(__fdividef(1.0f, plo), __fdividef(1.0f, phi));
    u64 r0 = f2clip(f2mul(f2mul(p0, t12), inv));
    u64 r1 = f2clip(f2mul(f2mul(p1, t02), inv));
    u64 r2 = f2clip(f2mul(f2mul(p2, t01), inv));
    u64 np0 = f2add(r0, ONE2), nm0 = f2fma(r0, NEG2, ONE2);
    u64 np1 = f2add(r1, ONE2), nm1 = f2fma(r1, NEG2, ONE2);
    u64 np2 = f2add(r2, ONE2), nm2 = f2fma(r2, NEG2, ONE2);
    u64 e0 = f2mul(el, np0);
    u64 A0 = f2mul(el, f2mul(np1, np2));
    u64 A1 = f2mul(e0, np2);
    u64 A2 = f2mul(e0, np1);
    u64 B0 = f2mul(nm1, nm2);
    u64 B1 = f2mul(nm0, nm2);
    u64 B2 = f2mul(nm0, nm1);
    o0 = f2msg(A0, B0);
    o1 = f2msg(A1, B1);
    o2 = f2msg(A2, B2);
}

// Final decision, one lane (scalar, runs once): bit = (el*Prod(np) < Prod(nm))
__device__ __forceinline__ float var_decide(float m0, float m1, float m2,
                                            float p0, float p1, float p2,
                                            float el) {
    float inv = __fdividef(1.0f, m0 * m1 * m2);
    float r0 = clip999(p0 * (m1 * m2) * inv);
    float r1 = clip999(p1 * (m0 * m2) * inv);
    float r2 = clip999(p2 * (m0 * m1) * inv);
    float U = el * ((1.0f + r0) * (1.0f + r1)) * (1.0f + r2);
    float D = ((1.0f - r0) * (1.0f - r1)) * (1.0f - r2);
    return (U < D) ? 1.0f : 0.0f;
}

// One check's product step (packed pairs)
__device__ __forceinline__ void check_step(int m, int o0, int o1,
                                           const float4* __restrict__ sT,
                                           const float4* __restrict__ sTp,
                                           float4* __restrict__ sP,
                                           const short* __restrict__ selist) {
    float4 tp = sTp[m];
    u64 pA = f2pack(tp.x, tp.y), pB = f2pack(tp.z, tp.w);
    for (int q = o0; q < o1; q++) {
        float4 tt = sT[selist[q]];
        pA = f2mul(pA, f2pack(tt.x, tt.y));
        pB = f2mul(pB, f2pack(tt.z, tt.w));
    }
    float4 p;
    f2unpack(pA, p.x, p.y); f2unpack(pB, p.z, p.w);
    sP[m] = p;
}

// One variable's full step (packed update or scalar final decision)
__device__ __forceinline__ void var_step(int v, int c0, int c1, int c2,
                                         float4* __restrict__ sT,
                                         const float4* __restrict__ sP,
                                         const float4* __restrict__ sEL,
                                         bool last, float* __restrict__ oh) {
    float4 m0 = sT[3 * v], m1 = sT[3 * v + 1], m2 = sT[3 * v + 2];
    float4 p0 = sP[c0], p1 = sP[c1], p2 = sP[c2];
    float4 el = sEL[v];
    if (!last) {
        u64 oa0, oa1, oa2, ob0, ob1, ob2;
        var_update_pair(f2pack(m0.x, m0.y), f2pack(m1.x, m1.y), f2pack(m2.x, m2.y),
                        f2pack(p0.x, p0.y), f2pack(p1.x, p1.y), f2pack(p2.x, p2.y),
                        f2pack(el.x, el.y), oa0, oa1, oa2);
        var_update_pair(f2pack(m0.z, m0.w), f2pack(m1.z, m1.w), f2pack(m2.z, m2.w),
                        f2pack(p0.z, p0.w), f2pack(p1.z, p1.w), f2pack(p2.z, p2.w),
                        f2pack(el.z, el.w), ob0, ob1, ob2);
        float4 o;
        f2unpack(oa0, o.x, o.y); f2unpack(ob0, o.z, o.w); sT[3 * v]     = o;
        f2unpack(oa1, o.x, o.y); f2unpack(ob1, o.z, o.w); sT[3 * v + 1] = o;
        f2unpack(oa2, o.x, o.y); f2unpack(ob2, o.z, o.w); sT[3 * v + 2] = o;
    } else {
        oh[0 * K_ + v] = var_decide(m0.x, m1.x, m2.x, p0.x, p1.x, p2.x, el.x);
        oh[1 * K_ + v] = var_decide(m0.y, m1.y, m2.y, p0.y, p1.y, p2.y, el.y);
        oh[2 * K_ + v] = var_decide(m0.z, m1.z, m2.z, p0.z, p1.z, p2.z, el.z);
        oh[3 * K_ + v] = var_decide(m0.w, m1.w, m2.w, p0.w, p1.w, p2.w, el.w);
    }
}

// ---------------------------------------------------------------------------
// Fused encode + LMMSE (R10/R14 code). Block 0 builds the CSR; parity via
// shared atomicXor over the raw cn edge list.
// ---------------------------------------------------------------------------
__global__ __launch_bounds__(256)
void enc_lmmse_kernel(const int* __restrict__ bin,
                      const int* __restrict__ cn,
                      const float4* __restrict__ hre4, const float4* __restrict__ him4,
                      const float4* __restrict__ nre4, const float4* __restrict__ nim4,
                      const float* __restrict__ ebno,
                      float* __restrict__ out_bf)
{
    __shared__ char scratch[12032];
    unsigned char* bits = (unsigned char*)scratch;      // [NUE_*N_] = 4000
    int* sp = (int*)(scratch + 4000);                   // [NUE_*M_] = 8000

    const int b = blockIdx.x;
    const int t = threadIdx.x;
    const int lane = t & 31, wid = t >> 5;

    if (b == 0) {
        int*   cnt  = (int*)scratch;            // [M_]   2000
        int*   base = (int*)(scratch + 2000);   // [M_]   2000
        int*   wsum = (int*)(scratch + 4000);   // [8]      32
        short* sel  = (short*)(scratch + 4032); // [NINFOE_] 3000

        for (int m = t; m < M_; m += 256) cnt[m] = 0;
        __syncthreads();
        for (int e = t; e < NINFOE_; e += 256) atomicAdd(&cnt[cn[e]], 1);
        __syncthreads();
        int v0 = (2 * t     < M_) ? cnt[2 * t]     : 0;
        int v1 = (2 * t + 1 < M_) ? cnt[2 * t + 1] : 0;
        int s = v0 + v1, x = s;
#pragma unroll
        for (int d = 1; d < 32; d <<= 1) {
            int nn = __shfl_up_sync(0xffffffffu, x, d);
            if (lane >= d) x += nn;
        }
        if (lane == 31) wsum[wid] = x;
        __syncthreads();
        if (wid == 0) {
            int s2 = (lane < 8) ? wsum[lane] : 0;
#pragma unroll
            for (int d = 1; d < 8; d <<= 1) {
                int nn = __shfl_up_sync(0xffffffffu, s2, d);
                if (lane >= d) s2 += nn;
            }
            if (lane < 8) wsum[lane] = s2;
        }
        __syncthreads();
        int ex = x + ((wid > 0) ? wsum[wid - 1] : 0) - s;
        if (2 * t     < M_) { base[2 * t]     = ex;      g_eoff[2 * t]     = (short)ex; }
        if (2 * t + 1 < M_) { base[2 * t + 1] = ex + v0; g_eoff[2 * t + 1] = (short)(ex + v0); }
        if (t == 0) g_eoff[M_] = (short)NINFOE_;
        __syncthreads();
        for (int m = t; m < M_; m += 256) cnt[m] = 0;
        __syncthreads();
        for (int e = t; e < NINFOE_; e += 256) {
            int c = cn[e];
            int sl = atomicAdd(&cnt[c], 1);
            sel[base[c] + sl] = (short)e;
        }
        __syncthreads();
        for (int m = t; m < M_; m += 256) {
            int o0 = base[m], o1 = o0 + cnt[m];
            for (int i = o0 + 1; i < o1; i++) {
                short vv = sel[i];
                int j = i - 1;
                while (j >= o0 && sel[j] > vv) { sel[j + 1] = sel[j]; j--; }
                sel[j + 1] = vv;
            }
        }
        __syncthreads();
        for (int e = t; e < NINFOE_; e += 256) g_elist[e] = sel[e];
        __syncthreads();
    }

    const int* bb = bin + (size_t)b * NUE_ * K_;
    float* of = out_bf + (size_t)b * NUE_ * K_;
    for (int i = t; i < NUE_ * K_; i += 256) {
        int ue = i / K_, n = i - ue * K_;
        int bit = bb[i];
        bits[ue * N_ + n] = (unsigned char)bit;
        of[i] = (float)bit;
    }
    for (int i = t; i < NUE_ * M_; i += 256) sp[i] = 0;
    __syncthreads();

    for (int e = t; e < NINFOE_; e += 256) {
        int c = cn[e], v = e / 3;
#pragma unroll
        for (int ue = 0; ue < 4; ue++)
            if (bits[ue * N_ + v]) atomicXor(&sp[ue * M_ + c], 1);
    }
    __syncthreads();
    for (int i = t; i < NUE_ * M_; i += 256) {
        int ue = i / M_, m = i - ue * M_;
        bits[ue * N_ + K_ + m] = (unsigned char)sp[i];
    }
    __syncthreads();

    if (t >= NSYM_) return;

    const float no  = 1.0f / (exp10f(ebno[0] * 0.1f) * 2.0f);
    const int r = b * NSYM_ + t;
    const float is2 = 0.70710678118654752440f;
    const float s10 = 0.31622776601683794f;

    float hr[4][4], hi[4][4];
#pragma unroll
    for (int i = 0; i < 4; i++) {
        float4 vr = hre4[r * 4 + i];
        float4 vi = him4[r * 4 + i];
        hr[i][0] = vr.x * is2; hr[i][1] = vr.y * is2; hr[i][2] = vr.z * is2; hr[i][3] = vr.w * is2;
        hi[i][0] = vi.x * is2; hi[i][1] = vi.y * is2; hi[i][2] = vi.z * is2; hi[i][3] = vi.w * is2;
    }

    float xr[4], xi[4];
#pragma unroll
    for (int j = 0; j < 4; j++) {
        uchar4 cb = *(const uchar4*)&bits[j * N_ + 4 * t];
        xr[j] = (float)((1 - 2 * (int)cb.x) * (1 + 2 * (int)cb.z)) * s10;
        xi[j] = (float)((1 - 2 * (int)cb.y) * (1 + 2 * (int)cb.w)) * s10;
    }

    const float ns = sqrtf(no * 0.5f);
    float4 wr4 = nre4[r], wi4 = nim4[r];
    float yr[4] = {wr4.x * ns, wr4.y * ns, wr4.z * ns, wr4.w * ns};
    float yi[4] = {wi4.x * ns, wi4.y * ns, wi4.z * ns, wi4.w * ns};
#pragma unroll
    for (int i = 0; i < 4; i++)
#pragma unroll
        for (int j = 0; j < 4; j++) {
            yr[i] += hr[i][j] * xr[j] - hi[i][j] * xi[j];
            yi[i] += hr[i][j] * xi[j] + hi[i][j] * xr[j];
        }

    float rr[4], ri[4];
#pragma unroll
    for (int j = 0; j < 4; j++) {
        float ar = 0.f, ai = 0.f;
#pragma unroll
        for (int i = 0; i < 4; i++) {
            ar += hr[i][j] * yr[i] + hi[i][j] * yi[i];
            ai += hr[i][j] * yi[i] - hi[i][j] * yr[i];
        }
        rr[j] = ar; ri[j] = ai;
    }

    float Br[4][4], Bi[4][4];
#pragma unroll
    for (int j = 0; j < 4; j++)
#pragma unroll
        for (int k = 0; k < 4; k++) {
            if (k > j) continue;
            float ar = (j == k) ? no : 0.f;
            float ai = 0.f;
#pragma unroll
            for (int i = 0; i < 4; i++) {
                ar += hr[i][j] * hr[i][k] + hi[i][j] * hi[i][k];
                ai += hr[i][j] * hi[i][k] - hi[i][j] * hr[i][k];
            }
            Br[j][k] = ar; Bi[j][k] = ai;
        }

    float rk[4];
#pragma unroll
    for (int k = 0; k < 4; k++) {
        float v = Br[k][k];
#pragma unroll
        for (int j = 0; j < 4; j++)
            if (j < k) v -= Br[k][j] * Br[k][j] + Bi[k][j] * Bi[k][j];
        float inv = rsqrtf(v);
        rk[k] = inv;
#pragma unroll
        for (int i = 0; i < 4; i++) {
            if (i <= k) continue;
            float cr = Br[i][k], ci = Bi[i][k];
#pragma unroll
            for (int j = 0; j < 4; j++)
                if (j < k) {
                    cr -= Br[i][j] * Br[k][j] + Bi[i][j] * Bi[k][j];
                    ci -= Bi[i][j] * Br[k][j] - Br[i][j] * Bi[k][j];
                }
            Br[i][k] = cr * inv; Bi[i][k] = ci * inv;
        }
    }

    float vr_[4], vi_[4];
#pragma unroll
    for (int i = 0; i < 4; i++) {
        float ar = rr[i], ai = ri[i];
#pragma unroll
        for (int j = 0; j < 4; j++)
            if (j < i) {
                ar -= Br[i][j] * vr_[j] - Bi[i][j] * vi_[j];
                ai -= Br[i][j] * vi_[j] + Bi[i][j] * vr_[j];
            }
        vr_[i] = ar * rk[i]; vi_[i] = ai * rk[i];
    }
    float xrw[4], xiw[4];
#pragma unroll
    for (int ii = 0; ii < 4; ii++) {
        int i = 3 - ii;
        float ar = vr_[i], ai = vi_[i];
#pragma unroll
        for (int j = 0; j < 4; j++)
            if (j > i) {
                ar -= Br[j][i] * xrw[j] + Bi[j][i] * xiw[j];
                ai -= Br[j][i] * xiw[j] - Bi[j][i] * xrw[j];
            }
        xrw[i] = ar * rk[i]; xiw[i] = ai * rk[i];
    }

    float dj[4];
#pragma unroll
    for (int j = 0; j < 4; j++) {
        float wr[4], wi[4];
#pragma unroll
        for (int i = 0; i < 4; i++) { wr[i] = 0.f; wi[i] = 0.f; }
        wr[j] = rk[j];
        float acc = rk[j] * rk[j];
#pragma unroll
        for (int i = 0; i < 4; i++) {
            if (i <= j) continue;
            float sr = 0.f, si = 0.f;
#pragma unroll
            for (int q = 0; q < 4; q++)
                if (q >= j && q < i) {
                    sr += Br[i][q] * wr[q] - Bi[i][q] * wi[q];
                    si += Br[i][q] * wi[q] + Bi[i][q] * wr[q];
                }
            wr[i] = -sr * rk[i]; wi[i] = -si * rk[i];
            acc += wr[i] * wr[i] + wi[i] * wi[i];
        }
        dj[j] = acc;
    }

#pragma unroll
    for (int c = 0; c < 4; c++) {
        float d = 1.0f - no * dj[c];
        float invd = 1.0f / d;
        float xhr = xrw[c] * invd, xhi = xiw[c] * invd;
        float noeff = fmaxf(invd - 1.0f, 1e-12f);
        float inoe = 1.0f / noeff;

        float a1  = xhr - s10,  a3  = xhr - 3.f * s10;
        float am1 = xhr + s10,  am3 = xhr + 3.f * s10;
        float f1 = -(a1 * a1), f3 = -(a3 * a3), fm1 = -(am1 * am1), fm3 = -(am3 * am3);
        float g1_ = xhi - s10,  g3_ = xhi - 3.f * s10;
        float gm1_ = xhi + s10, gm3_ = xhi + 3.f * s10;
        float g1 = -(g1_ * g1_), g3 = -(g3_ * g3_), gm1 = -(gm1_ * gm1_), gm3 = -(gm3_ * gm3_);

        float4 out = make_float4((fmaxf(f1, f3)  - fmaxf(fm1, fm3)) * inoe,
                                 (fmaxf(g1, g3)  - fmaxf(gm1, gm3)) * inoe,
                                 (fmaxf(f1, fm1) - fmaxf(f3, fm3))  * inoe,
                                 (fmaxf(g1, gm1) - fmaxf(g3, gm3))  * inoe);
        *(float4*)&g_llr[(size_t)(b * NUE_ + c) * N_ + 4 * t] = out;
    }
}

// ---------------------------------------------------------------------------
// Decoder: one block per batch element, 256 threads, 2 variables + 2 checks
// per thread (R14 structure), with packed f32x2 arithmetic in the hot loops.
// ---------------------------------------------------------------------------
extern __shared__ unsigned char dynsmem[];
#define DEC_SMEM (24000 + 8000 + 8000 + 8000 + 3000)

__global__ __launch_bounds__(256, 4)
void decode_kernel(const int* __restrict__ cn, float* __restrict__ out_bhat) {
    float4* sT  = (float4*)dynsmem;          // [NINFOE_] v->c message tanh
    float4* sP  = sT + NINFOE_;              // [M_]  check products
    float4* sTp = sP + M_;                   // [M_]  parity-edge tanh (invariant)
    float4* sEL = sTp + M_;                  // [K_]  clamped exp(Lch)
    short* selist = (short*)(sEL + K_);      // [NINFOE_]

    const int b = blockIdx.x;
    const int t = threadIdx.x;
    const float* Lb = g_llr + (size_t)b * NUE_ * N_;

    for (int e = t; e < NINFOE_; e += 256) selist[e] = g_elist[e];

    for (int v = t; v < K_; v += 256) {
        float4 l;
        l.x = Lb[0 * N_ + v]; l.y = Lb[1 * N_ + v];
        l.z = Lb[2 * N_ + v]; l.w = Lb[3 * N_ + v];
        float4 el;
        el.x = fminf(__expf(l.x), 1e30f); el.y = fminf(__expf(l.y), 1e30f);
        el.z = fminf(__expf(l.z), 1e30f); el.w = fminf(__expf(l.w), 1e30f);
        sEL[v] = el;
        float4 m;
        m.x = tanh_clip_half(l.x * 0.5f);
        m.y = tanh_clip_half(l.y * 0.5f);
        m.z = tanh_clip_half(l.z * 0.5f);
        m.w = tanh_clip_half(l.w * 0.5f);
        sT[3 * v] = m; sT[3 * v + 1] = m; sT[3 * v + 2] = m;
    }
    for (int m = t; m < M_; m += 256) {
        float4 lp;
        lp.x = Lb[0 * N_ + K_ + m]; lp.y = Lb[1 * N_ + K_ + m];
        lp.z = Lb[2 * N_ + K_ + m]; lp.w = Lb[3 * N_ + K_ + m];
        float4 tp;
        tp.x = tanh_clip_half(lp.x * 0.5f);
        tp.y = tanh_clip_half(lp.y * 0.5f);
        tp.z = tanh_clip_half(lp.z * 0.5f);
        tp.w = tanh_clip_half(lp.w * 0.5f);
        sTp[m] = tp;
    }

    const bool hasB = (t + 256 < K_);   // K_ == M_ == 500
    const int vA = t, vB = t + 256;
    int c0a = cn[3 * vA], c1a = cn[3 * vA + 1], c2a = cn[3 * vA + 2];
    int c0b = 0, c1b = 0, c2b = 0;
    if (hasB) { c0b = cn[3 * vB]; c1b = cn[3 * vB + 1]; c2b = cn[3 * vB + 2]; }
    int coa0 = g_eoff[vA], coa1 = g_eoff[vA + 1];
    int cob0 = 0, cob1 = 0;
    if (hasB) { cob0 = g_eoff[vB]; cob1 = g_eoff[vB + 1]; }
    __syncthreads();

    float* oh = out_bhat + (size_t)b * NUE_ * K_;

    for (int it = 0; it < NITER_; it++) {
        check_step(vA, coa0, coa1, sT, sTp, sP, selist);
        if (hasB) check_step(vB, cob0, cob1, sT, sTp, sP, selist);
        __syncthreads();
        bool last = (it == NITER_ - 1);
        var_step(vA, c0a, c1a, c2a, sT, sP, sEL, last, oh);
        if (hasB) var_step(vB, c0b, c1b, c2b, sT, sP, sEL, last, oh);
        if (!last) __syncthreads();
    }
}

// ---------------------------------------------------------------------------
extern "C" void kernel_launch(void* const* d_in, const int* in_sizes, int n_in,
                              void* d_out, int out_size) {
    int shift = 10 - n_in;
    const float* ebno = (const float*)d_in[1 - shift];
    const int*   b    = (const int*)  d_in[2 - shift];
    const int*   cn   = (const int*)  d_in[4 - shift];
    const float* h_re = (const float*)d_in[6 - shift];
    const float* h_im = (const float*)d_in[7 - shift];
    const float* n_re = (const float*)d_in[8 - shift];
    const float* n_im = (const float*)d_in[9 - shift];

    float* out_bf = (float*)d_out;                       // (batch, NUE, K)
    float* out_bh = (float*)d_out + BATCH * NUE_ * K_;   // (batch, NUE, K)

    cudaFuncSetAttribute(decode_kernel, cudaFuncAttributeMaxDynamicSharedMemorySize, DEC_SMEM);

    enc_lmmse_kernel<<<BATCH, 256>>>(b, cn,
                                     (const float4*)h_re, (const float4*)h_im,
                                     (const float4*)n_re, (const float4*)n_im,
                                     ebno, out_bf);
    decode_kernel<<<BATCH, 256, DEC_SMEM>>>(cn, out_bh);
}

// round 17
// speedup vs baseline: 1.0625x; 1.0091x over previous
#include <cuda_runtime.h>

// Problem constants (fixed by reference)
#define BATCH   1000
#define NUE_    4
#define K_      500
#define M_      500
#define N_      1000
#define NSYM_   250
#define NEDGE_  2000
#define NINFOE_ 1500
#define NITER_  5

typedef unsigned long long u64;
#define ONE2 0x3F8000003F800000ULL   // pack(1.0f, 1.0f)
#define NEG2 0xBF800000BF800000ULL   // pack(-1.0f, -1.0f)

// Static scratch
__device__ float g_llr[BATCH * NUE_ * N_];   // channel LLRs
__device__ short g_eoff[M_ + 1];
__device__ short g_elist[NINFOE_];

// ---------------------------------------------------------------------------
// Packed f32x2 helpers (R16-validated)
// ---------------------------------------------------------------------------
__device__ __forceinline__ u64 f2pack(float lo, float hi) {
    u64 r; asm("mov.b64 %0, {%1, %2};" : "=l"(r) : "f"(lo), "f"(hi)); return r;
}
__device__ __forceinline__ void f2unpack(u64 v, float& lo, float& hi) {
    asm("mov.b64 {%0, %1}, %2;" : "=f"(lo), "=f"(hi) : "l"(v));
}
__device__ __forceinline__ u64 f2mul(u64 a, u64 b) {
    u64 r; asm("mul.rn.f32x2 %0, %1, %2;" : "=l"(r) : "l"(a), "l"(b)); return r;
}
__device__ __forceinline__ u64 f2add(u64 a, u64 b) {
    u64 r; asm("add.rn.f32x2 %0, %1, %2;" : "=l"(r) : "l"(a), "l"(b)); return r;
}
__device__ __forceinline__ u64 f2fma(u64 a, u64 b, u64 c) {
    u64 r; asm("fma.rn.f32x2 %0, %1, %2, %3;" : "=l"(r) : "l"(a), "l"(b), "l"(c)); return r;
}

// ---------------------------------------------------------------------------
// Hybrid tanh (validated R3-R16) — init only.
// ---------------------------------------------------------------------------
__device__ __forceinline__ float tanh_clip_half(float x) {
    x = fminf(fmaxf(x, -9.9f), 9.9f);
    float ax = fabsf(x);
    float x2 = x * x;
    float num = x * fmaf(x2, fmaf(x2, 1.0f, 105.0f), 945.0f);
    float den = fmaf(x2, fmaf(x2, 15.0f, 420.0f), 945.0f);
    float tp  = __fdividef(num, den);
    float e   = __expf(2.0f * ax);
    float te  = copysignf(1.0f - __fdividef(2.0f, e + 1.0f), x);
    float t   = (ax < 1.0f) ? tp : te;
    return (t >= 0.f) ? fmaxf(t, 1e-7f) : fminf(t, -1e-7f);
}

__device__ __forceinline__ float clip999(float x) {
    return fminf(fmaxf(x, -0.999999f), 0.999999f);
}
__device__ __forceinline__ float msg_floor(float t) {
    return (t >= 0.f) ? fmaxf(t, 1e-7f) : fminf(t, -1e-7f);
}
__device__ __forceinline__ u64 f2clip(u64 v) {
    float lo, hi; f2unpack(v, lo, hi);
    return f2pack(clip999(lo), clip999(hi));
}
__device__ __forceinline__ u64 f2msg(u64 A, u64 B) {
    u64 num = f2fma(B, NEG2, A);
    u64 den = f2add(A, B);
    float nlo, nhi, dlo, dhi;
    f2unpack(num, nlo, nhi); f2unpack(den, dlo, dhi);
    return f2pack(msg_floor(__fdividef(nlo, dlo)), msg_floor(__fdividef(nhi, dhi)));
}

// Variable update for a LANE PAIR (R16 code, byte-identical behavior)
__device__ __forceinline__ void var_update_pair(u64 m0, u64 m1, u64 m2,
                                                u64 p0, u64 p1, u64 p2, u64 el,
                                                u64& o0, u64& o1, u64& o2) {
    u64 t12 = f2mul(m1, m2);
    u64 t02 = f2mul(m0, m2);
    u64 t01 = f2mul(m0, m1);
    u64 pr  = f2mul(t01, m2);
    float plo, phi; f2unpack(pr, plo, phi);
    u64 inv = f2pack(__fdividef(1.0f, plo), __fdividef(1.0f, phi));
    u64 r0 = f2clip(f2mul(f2mul(p0, t12), inv));
    u64 r1 = f2clip(f2mul(f2mul(p1, t02), inv));
    u64 r2 = f2clip(f2mul(f2mul(p2, t01), inv));
    u64 np0 = f2add(r0, ONE2), nm0 = f2fma(r0, NEG2, ONE2);
    u64 np1 = f2add(r1, ONE2), nm1 = f2fma(r1, NEG2, ONE2);
    u64 np2 = f2add(r2, ONE2), nm2 = f2fma(r2, NEG2, ONE2);
    u64 e0 = f2mul(el, np0);
    u64 A0 = f2mul(el, f2mul(np1, np2));
    u64 A1 = f2mul(e0, np2);
    u64 A2 = f2mul(e0, np1);
    u64 B0 = f2mul(nm1, nm2);
    u64 B1 = f2mul(nm0, nm2);
    u64 B2 = f2mul(nm0, nm1);
    o0 = f2msg(A0, B0);
    o1 = f2msg(A1, B1);
    o2 = f2msg(A2, B2);
}

// Final decision, one lane (scalar)
__device__ __forceinline__ float var_decide(float m0, float m1, float m2,
                                            float p0, float p1, float p2,
                                            float el) {
    float inv = __fdividef(1.0f, m0 * m1 * m2);
    float r0 = clip999(p0 * (m1 * m2) * inv);
    float r1 = clip999(p1 * (m0 * m2) * inv);
    float r2 = clip999(p2 * (m0 * m1) * inv);
    float U = el * ((1.0f + r0) * (1.0f + r1)) * (1.0f + r2);
    float D = ((1.0f - r0) * (1.0f - r1)) * (1.0f - r2);
    return (U < D) ? 1.0f : 0.0f;
}

// One check's product step (packed pairs)
__device__ __forceinline__ void check_step(int m, int o0, int o1,
                                           const float4* __restrict__ sT,
                                           const float4* __restrict__ sTp,
                                           float4* __restrict__ sP,
                                           const short* __restrict__ selist) {
    float4 tp = sTp[m];
    u64 pA = f2pack(tp.x, tp.y), pB = f2pack(tp.z, tp.w);
    for (int q = o0; q < o1; q++) {
        float4 tt = sT[selist[q]];
        pA = f2mul(pA, f2pack(tt.x, tt.y));
        pB = f2mul(pB, f2pack(tt.z, tt.w));
    }
    float4 p;
    f2unpack(pA, p.x, p.y); f2unpack(pB, p.z, p.w);
    sP[m] = p;
}

// One variable's full step
__device__ __forceinline__ void var_step(int v, int c0, int c1, int c2,
                                         float4* __restrict__ sT,
                                         const float4* __restrict__ sP,
                                         const float4* __restrict__ sEL,
                                         bool last, float* __restrict__ oh) {
    float4 m0 = sT[3 * v], m1 = sT[3 * v + 1], m2 = sT[3 * v + 2];
    float4 p0 = sP[c0], p1 = sP[c1], p2 = sP[c2];
    float4 el = sEL[v];
    if (!last) {
        u64 oa0, oa1, oa2, ob0, ob1, ob2;
        var_update_pair(f2pack(m0.x, m0.y), f2pack(m1.x, m1.y), f2pack(m2.x, m2.y),
                        f2pack(p0.x, p0.y), f2pack(p1.x, p1.y), f2pack(p2.x, p2.y),
                        f2pack(el.x, el.y), oa0, oa1, oa2);
        var_update_pair(f2pack(m0.z, m0.w), f2pack(m1.z, m1.w), f2pack(m2.z, m2.w),
                        f2pack(p0.z, p0.w), f2pack(p1.z, p1.w), f2pack(p2.z, p2.w),
                        f2pack(el.z, el.w), ob0, ob1, ob2);
        float4 o;
        f2unpack(oa0, o.x, o.y); f2unpack(ob0, o.z, o.w); sT[3 * v]     = o;
        f2unpack(oa1, o.x, o.y); f2unpack(ob1, o.z, o.w); sT[3 * v + 1] = o;
        f2unpack(oa2, o.x, o.y); f2unpack(ob2, o.z, o.w); sT[3 * v + 2] = o;
    } else {
        oh[0 * K_ + v] = var_decide(m0.x, m1.x, m2.x, p0.x, p1.x, p2.x, el.x);
        oh[1 * K_ + v] = var_decide(m0.y, m1.y, m2.y, p0.y, p1.y, p2.y, el.y);
        oh[2 * K_ + v] = var_decide(m0.z, m1.z, m2.z, p0.z, p1.z, p2.z, el.z);
        oh[3 * K_ + v] = var_decide(m0.w, m1.w, m2.w, p0.w, p1.w, p2.w, el.w);
    }
}

// ---------------------------------------------------------------------------
// Fused encode + LMMSE. Grid = BATCH + 1: block 0 does ONLY the CSR build
// (was serialized in front of block 0's batch work -> whole-kernel straggler);
// blocks 1..BATCH handle batch b = blockIdx.x - 1. CSR code and edge order
// unchanged -> g_eoff/g_elist and all g_llr values bit-identical to R16.
// ---------------------------------------------------------------------------
__global__ __launch_bounds__(256)
void enc_lmmse_kernel(const int* __restrict__ bin,
                      const int* __restrict__ cn,
                      const float4* __restrict__ hre4, const float4* __restrict__ him4,
                      const float4* __restrict__ nre4, const float4* __restrict__ nim4,
                      const float* __restrict__ ebno,
                      float* __restrict__ out_bf)
{
    __shared__ char scratch[12032];

    const int t = threadIdx.x;
    const int lane = t & 31, wid = t >> 5;

    if (blockIdx.x == 0) {
        // ---- dedicated CSR-build block ----
        int*   cnt  = (int*)scratch;            // [M_]   2000
        int*   base = (int*)(scratch + 2000);   // [M_]   2000
        int*   wsum = (int*)(scratch + 4000);   // [8]      32
        short* sel  = (short*)(scratch + 4032); // [NINFOE_] 3000

        for (int m = t; m < M_; m += 256) cnt[m] = 0;
        __syncthreads();
        for (int e = t; e < NINFOE_; e += 256) atomicAdd(&cnt[cn[e]], 1);
        __syncthreads();
        int v0 = (2 * t     < M_) ? cnt[2 * t]     : 0;
        int v1 = (2 * t + 1 < M_) ? cnt[2 * t + 1] : 0;
        int s = v0 + v1, x = s;
#pragma unroll
        for (int d = 1; d < 32; d <<= 1) {
            int nn = __shfl_up_sync(0xffffffffu, x, d);
            if (lane >= d) x += nn;
        }
        if (lane == 31) wsum[wid] = x;
        __syncthreads();
        if (wid == 0) {
            int s2 = (lane < 8) ? wsum[lane] : 0;
#pragma unroll
            for (int d = 1; d < 8; d <<= 1) {
                int nn = __shfl_up_sync(0xffffffffu, s2, d);
                if (lane >= d) s2 += nn;
            }
            if (lane < 8) wsum[lane] = s2;
        }
        __syncthreads();
        int ex = x + ((wid > 0) ? wsum[wid - 1] : 0) - s;
        if (2 * t     < M_) { base[2 * t]     = ex;      g_eoff[2 * t]     = (short)ex; }
        if (2 * t + 1 < M_) { base[2 * t + 1] = ex + v0; g_eoff[2 * t + 1] = (short)(ex + v0); }
        if (t == 0) g_eoff[M_] = (short)NINFOE_;
        __syncthreads();
        for (int m = t; m < M_; m += 256) cnt[m] = 0;
        __syncthreads();
        for (int e = t; e < NINFOE_; e += 256) {
            int c = cn[e];
            int sl = atomicAdd(&cnt[c], 1);
            sel[base[c] + sl] = (short)e;
        }
        __syncthreads();
        for (int m = t; m < M_; m += 256) {
            int o0 = base[m], o1 = o0 + cnt[m];
            for (int i = o0 + 1; i < o1; i++) {
                short vv = sel[i];
                int j = i - 1;
                while (j >= o0 && sel[j] > vv) { sel[j + 1] = sel[j]; j--; }
                sel[j + 1] = vv;
            }
        }
        __syncthreads();
        for (int e = t; e < NINFOE_; e += 256) g_elist[e] = sel[e];
        return;
    }

    const int b = blockIdx.x - 1;
    unsigned char* bits = (unsigned char*)scratch;      // [NUE_*N_] = 4000
    int* sp = (int*)(scratch + 4000);                   // [NUE_*M_] = 8000

    const int* bb = bin + (size_t)b * NUE_ * K_;
    float* of = out_bf + (size_t)b * NUE_ * K_;
    for (int i = t; i < NUE_ * K_; i += 256) {
        int ue = i / K_, n = i - ue * K_;
        int bit = bb[i];
        bits[ue * N_ + n] = (unsigned char)bit;
        of[i] = (float)bit;
    }
    for (int i = t; i < NUE_ * M_; i += 256) sp[i] = 0;
    __syncthreads();

    for (int e = t; e < NINFOE_; e += 256) {
        int c = cn[e], v = e / 3;
#pragma unroll
        for (int ue = 0; ue < 4; ue++)
            if (bits[ue * N_ + v]) atomicXor(&sp[ue * M_ + c], 1);
    }
    __syncthreads();
    for (int i = t; i < NUE_ * M_; i += 256) {
        int ue = i / M_, m = i - ue * M_;
        bits[ue * N_ + K_ + m] = (unsigned char)sp[i];
    }
    __syncthreads();

    if (t >= NSYM_) return;

    const float no  = 1.0f / (exp10f(ebno[0] * 0.1f) * 2.0f);
    const int r = b * NSYM_ + t;
    const float is2 = 0.70710678118654752440f;
    const float s10 = 0.31622776601683794f;

    float hr[4][4], hi[4][4];
#pragma unroll
    for (int i = 0; i < 4; i++) {
        float4 vr = hre4[r * 4 + i];
        float4 vi = him4[r * 4 + i];
        hr[i][0] = vr.x * is2; hr[i][1] = vr.y * is2; hr[i][2] = vr.z * is2; hr[i][3] = vr.w * is2;
        hi[i][0] = vi.x * is2; hi[i][1] = vi.y * is2; hi[i][2] = vi.z * is2; hi[i][3] = vi.w * is2;
    }

    float xr[4], xi[4];
#pragma unroll
    for (int j = 0; j < 4; j++) {
        uchar4 cb = *(const uchar4*)&bits[j * N_ + 4 * t];
        xr[j] = (float)((1 - 2 * (int)cb.x) * (1 + 2 * (int)cb.z)) * s10;
        xi[j] = (float)((1 - 2 * (int)cb.y) * (1 + 2 * (int)cb.w)) * s10;
    }

    const float ns = sqrtf(no * 0.5f);
    float4 wr4 = nre4[r], wi4 = nim4[r];
    float yr[4] = {wr4.x * ns, wr4.y * ns, wr4.z * ns, wr4.w * ns};
    float yi[4] = {wi4.x * ns, wi4.y * ns, wi4.z * ns, wi4.w * ns};
#pragma unroll
    for (int i = 0; i < 4; i++)
#pragma unroll
        for (int j = 0; j < 4; j++) {
            yr[i] += hr[i][j] * xr[j] - hi[i][j] * xi[j];
            yi[i] += hr[i][j] * xi[j] + hi[i][j] * xr[j];
        }

    float rr[4], ri[4];
#pragma unroll
    for (int j = 0; j < 4; j++) {
        float ar = 0.f, ai = 0.f;
#pragma unroll
        for (int i = 0; i < 4; i++) {
            ar += hr[i][j] * yr[i] + hi[i][j] * yi[i];
            ai += hr[i][j] * yi[i] - hi[i][j] * yr[i];
        }
        rr[j] = ar; ri[j] = ai;
    }

    float Br[4][4], Bi[4][4];
#pragma unroll
    for (int j = 0; j < 4; j++)
#pragma unroll
        for (int k = 0; k < 4; k++) {
            if (k > j) continue;
            float ar = (j == k) ? no : 0.f;
            float ai = 0.f;
#pragma unroll
            for (int i = 0; i < 4; i++) {
                ar += hr[i][j] * hr[i][k] + hi[i][j] * hi[i][k];
                ai += hr[i][j] * hi[i][k] - hi[i][j] * hr[i][k];
            }
            Br[j][k] = ar; Bi[j][k] = ai;
        }

    float rk[4];
#pragma unroll
    for (int k = 0; k < 4; k++) {
        float v = Br[k][k];
#pragma unroll
        for (int j = 0; j < 4; j++)
            if (j < k) v -= Br[k][j] * Br[k][j] + Bi[k][j] * Bi[k][j];
        float inv = rsqrtf(v);
        rk[k] = inv;
#pragma unroll
        for (int i = 0; i < 4; i++) {
            if (i <= k) continue;
            float cr = Br[i][k], ci = Bi[i][k];
#pragma unroll
            for (int j = 0; j < 4; j++)
                if (j < k) {
                    cr -= Br[i][j] * Br[k][j] + Bi[i][j] * Bi[k][j];
                    ci -= Bi[i][j] * Br[k][j] - Br[i][j] * Bi[k][j];
                }
            Br[i][k] = cr * inv; Bi[i][k] = ci * inv;
        }
    }

    float vr_[4], vi_[4];
#pragma unroll
    for (int i = 0; i < 4; i++) {
        float ar = rr[i], ai = ri[i];
#pragma unroll
        for (int j = 0; j < 4; j++)
            if (j < i) {
                ar -= Br[i][j] * vr_[j] - Bi[i][j] * vi_[j];
                ai -= Br[i][j] * vi_[j] + Bi[i][j] * vr_[j];
            }
        vr_[i] = ar * rk[i]; vi_[i] = ai * rk[i];
    }
    float xrw[4], xiw[4];
#pragma unroll
    for (int ii = 0; ii < 4; ii++) {
        int i = 3 - ii;
        float ar = vr_[i], ai = vi_[i];
#pragma unroll
        for (int j = 0; j < 4; j++)
            if (j > i) {
                ar -= Br[j][i] * xrw[j] + Bi[j][i] * xiw[j];
                ai -= Br[j][i] * xiw[j] - Bi[j][i] * xrw[j];
            }
        xrw[i] = ar * rk[i]; xiw[i] = ai * rk[i];
    }

    float dj[4];
#pragma unroll
    for (int j = 0; j < 4; j++) {
        float wr[4], wi[4];
#pragma unroll
        for (int i = 0; i < 4; i++) { wr[i] = 0.f; wi[i] = 0.f; }
        wr[j] = rk[j];
        float acc = rk[j] * rk[j];
#pragma unroll
        for (int i = 0; i < 4; i++) {
            if (i <= j) continue;
            float sr = 0.f, si = 0.f;
#pragma unroll
            for (int q = 0; q < 4; q++)
                if (q >= j && q < i) {
                    sr += Br[i][q] * wr[q] - Bi[i][q] * wi[q];
                    si += Br[i][q] * wi[q] + Bi[i][q] * wr[q];
                }
            wr[i] = -sr * rk[i]; wi[i] = -si * rk[i];
            acc += wr[i] * wr[i] + wi[i] * wi[i];
        }
        dj[j] = acc;
    }

#pragma unroll
    for (int c = 0; c < 4; c++) {
        float d = 1.0f - no * dj[c];
        float invd = 1.0f / d;
        float xhr = xrw[c] * invd, xhi = xiw[c] * invd;
        float noeff = fmaxf(invd - 1.0f, 1e-12f);
        float inoe = 1.0f / noeff;

        float a1  = xhr - s10,  a3  = xhr - 3.f * s10;
        float am1 = xhr + s10,  am3 = xhr + 3.f * s10;
        float f1 = -(a1 * a1), f3 = -(a3 * a3), fm1 = -(am1 * am1), fm3 = -(am3 * am3);
        float g1_ = xhi - s10,  g3_ = xhi - 3.f * s10;
        float gm1_ = xhi + s10, gm3_ = xhi + 3.f * s10;
        float g1 = -(g1_ * g1_), g3 = -(g3_ * g3_), gm1 = -(gm1_ * gm1_), gm3 = -(gm3_ * gm3_);

        float4 out = make_float4((fmaxf(f1, f3)  - fmaxf(fm1, fm3)) * inoe,
                                 (fmaxf(g1, g3)  - fmaxf(gm1, gm3)) * inoe,
                                 (fmaxf(f1, fm1) - fmaxf(f3, fm3))  * inoe,
                                 (fmaxf(g1, gm1) - fmaxf(g3, gm3))  * inoe);
        *(float4*)&g_llr[(size_t)(b * NUE_ + c) * N_ + 4 * t] = out;
    }
}

// ---------------------------------------------------------------------------
// Decoder (byte-identical to R16): one block per batch element, 256 threads,
// 2 variables + 2 checks per thread, packed f32x2 hot loops.
// ---------------------------------------------------------------------------
extern __shared__ unsigned char dynsmem[];
#define DEC_SMEM (24000 + 8000 + 8000 + 8000 + 3000)

__global__ __launch_bounds__(256, 4)
void decode_kernel(const int* __restrict__ cn, float* __restrict__ out_bhat) {
    float4* sT  = (float4*)dynsmem;          // [NINFOE_] v->c message tanh
    float4* sP  = sT + NINFOE_;              // [M_]  check products
    float4* sTp = sP + M_;                   // [M_]  parity-edge tanh (invariant)
    float4* sEL = sTp + M_;                  // [K_]  clamped exp(Lch)
    short* selist = (short*)(sEL + K_);      // [NINFOE_]

    const int b = blockIdx.x;
    const int t = threadIdx.x;
    const float* Lb = g_llr + (size_t)b * NUE_ * N_;

    for (int e = t; e < NINFOE_; e += 256) selist[e] = g_elist[e];

    for (int v = t; v < K_; v += 256) {
        float4 l;
        l.x = Lb[0 * N_ + v]; l.y = Lb[1 * N_ + v];
        l.z = Lb[2 * N_ + v]; l.w = Lb[3 * N_ + v];
        float4 el;
        el.x = fminf(__expf(l.x), 1e30f); el.y = fminf(__expf(l.y), 1e30f);
        el.z = fminf(__expf(l.z), 1e30f); el.w = fminf(__expf(l.w), 1e30f);
        sEL[v] = el;
        float4 m;
        m.x = tanh_clip_half(l.x * 0.5f);
        m.y = tanh_clip_half(l.y * 0.5f);
        m.z = tanh_clip_half(l.z * 0.5f);
        m.w = tanh_clip_half(l.w * 0.5f);
        sT[3 * v] = m; sT[3 * v + 1] = m; sT[3 * v + 2] = m;
    }
    for (int m = t; m < M_; m += 256) {
        float4 lp;
        lp.x = Lb[0 * N_ + K_ + m]; lp.y = Lb[1 * N_ + K_ + m];
        lp.z = Lb[2 * N_ + K_ + m]; lp.w = Lb[3 * N_ + K_ + m];
        float4 tp;
        tp.x = tanh_clip_half(lp.x * 0.5f);
        tp.y = tanh_clip_half(lp.y * 0.5f);
        tp.z = tanh_clip_half(lp.z * 0.5f);
        tp.w = tanh_clip_half(lp.w * 0.5f);
        sTp[m] = tp;
    }

    const bool hasB = (t + 256 < K_);   // K_ == M_ == 500
    const int vA = t, vB = t + 256;
    int c0a = cn[3 * vA], c1a = cn[3 * vA + 1], c2a = cn[3 * vA + 2];
    int c0b = 0, c1b = 0, c2b = 0;
    if (hasB) { c0b = cn[3 * vB]; c1b = cn[3 * vB + 1]; c2b = cn[3 * vB + 2]; }
    int coa0 = g_eoff[vA], coa1 = g_eoff[vA + 1];
    int cob0 = 0, cob1 = 0;
    if (hasB) { cob0 = g_eoff[vB]; cob1 = g_eoff[vB + 1]; }
    __syncthreads();

    float* oh = out_bhat + (size_t)b * NUE_ * K_;

    for (int it = 0; it < NITER_; it++) {
        check_step(vA, coa0, coa1, sT, sTp, sP, selist);
        if (hasB) check_step(vB, cob0, cob1, sT, sTp, sP, selist);
        __syncthreads();
        bool last = (it == NITER_ - 1);
        var_step(vA, c0a, c1a, c2a, sT, sP, sEL, last, oh);
        if (hasB) var_step(vB, c0b, c1b, c2b, sT, sP, sEL, last, oh);
        if (!last) __syncthreads();
    }
}

// ---------------------------------------------------------------------------
extern "C" void kernel_launch(void* const* d_in, const int* in_sizes, int n_in,
                              void* d_out, int out_size) {
    int shift = 10 - n_in;
    const float* ebno = (const float*)d_in[1 - shift];
    const int*   b    = (const int*)  d_in[2 - shift];
    const int*   cn   = (const int*)  d_in[4 - shift];
    const float* h_re = (const float*)d_in[6 - shift];
    const float* h_im = (const float*)d_in[7 - shift];
    const float* n_re = (const float*)d_in[8 - shift];
    const float* n_im = (const float*)d_in[9 - shift];

    float* out_bf = (float*)d_out;                       // (batch, NUE, K)
    float* out_bh = (float*)d_out + BATCH * NUE_ * K_;   // (batch, NUE, K)

    cudaFuncSetAttribute(decode_kernel, cudaFuncAttributeMaxDynamicSharedMemorySize, DEC_SMEM);

    enc_lmmse_kernel<<<BATCH + 1, 256>>>(b, cn,
                                         (const float4*)h_re, (const float4*)h_im,
                                         (const float4*)n_re, (const float4*)n_im,
                                         ebno, out_bf);
    decode_kernel<<<BATCH, 256, DEC_SMEM>>>(cn, out_bh);
}